// round 14
// baseline (speedup 1.0000x reference)
#include <cuda_runtime.h>
#include <cuda_fp16.h>
#include <math.h>
#include <stdint.h>

#define BB 2
#define HH 16
#define SS 2048
#define DH 64
#define DM 1024
#define MM (BB*SS)   // 4096

// ---------------------------------------------------------------------------
// Scratch (device globals)
// ---------------------------------------------------------------------------
__device__ __align__(256) __half g_xf[(size_t)MM*DM];
__device__ __align__(256) __half g_w4[4][(size_t)DM*DM];  // wq,wk,wv,wo [N,K]
// Q,K fp16 [B,H,S,DH] (Q pre-scaled by 1/8); V fp16 transposed [B,H,DH,S]
__device__ __align__(256) __half g_qf[(size_t)MM*DM];
__device__ __align__(256) __half g_kf[(size_t)MM*DM];
__device__ __align__(256) __half g_vf[(size_t)MM*DM];
// ctx fp16 (flash epilogue), row-major [MM, DM]
__device__ __align__(256) __half g_cf[(size_t)MM*DM];

// ---------------------------------------------------------------------------
// PTX helpers
// ---------------------------------------------------------------------------
__device__ __forceinline__ uint32_t smem_u32(const void* p) {
    uint32_t a;
    asm("{ .reg .u64 t; cvta.to.shared.u64 t, %1; cvt.u32.u64 %0, t; }"
        : "=r"(a) : "l"(p));
    return a;
}
__device__ __forceinline__ void cpa16(uint32_t s, const void* g) {
    asm volatile("cp.async.cg.shared.global [%0], [%1], 16;" :: "r"(s), "l"(g));
}
__device__ __forceinline__ void cpa_commit() {
    asm volatile("cp.async.commit_group;" ::: "memory");
}
__device__ __forceinline__ void ldmx4(uint32_t* r, uint32_t addr) {
    asm volatile("ldmatrix.sync.aligned.m8n8.x4.shared.b16 {%0,%1,%2,%3}, [%4];"
                 : "=r"(r[0]), "=r"(r[1]), "=r"(r[2]), "=r"(r[3]) : "r"(addr));
}
__device__ __forceinline__ void mmaf16(float* c, const uint32_t* a,
                                       uint32_t b0, uint32_t b1) {
    asm volatile(
        "mma.sync.aligned.m16n8k16.row.col.f32.f16.f16.f32 "
        "{%0,%1,%2,%3}, {%4,%5,%6,%7}, {%8,%9}, {%0,%1,%2,%3};"
        : "+f"(c[0]), "+f"(c[1]), "+f"(c[2]), "+f"(c[3])
        : "r"(a[0]), "r"(a[1]), "r"(a[2]), "r"(a[3]), "r"(b0), "r"(b1));
}
__device__ __forceinline__ uint32_t packh(float lo, float hi) {
    __half2 h = __floats2half2_rn(lo, hi);
    return *reinterpret_cast<uint32_t*>(&h);
}

// ---------------------------------------------------------------------------
// Fused prep: blocks [0,4096): x fp32->fp16; [4096,8192): weight transpose.
// ---------------------------------------------------------------------------
__global__ void prep_kernel(const float* __restrict__ x,
                            const float* __restrict__ wq,
                            const float* __restrict__ wk,
                            const float* __restrict__ wv,
                            const float* __restrict__ wo)
{
    int b = blockIdx.x;
    if (b < 4096) {
        int i = (b * 256 + threadIdx.x) * 4;
        float4 v = *(const float4*)(x + i);
        __half2 h0 = __floats2half2_rn(v.x, v.y);
        __half2 h1 = __floats2half2_rn(v.z, v.w);
        ((__half2*)(g_xf + i))[0] = h0;
        ((__half2*)(g_xf + i))[1] = h1;
        return;
    }
    __shared__ float t[32][33];
    int r = b - 4096;
    int w = r >> 10;
    int tl = r & 1023;
    int n0 = (tl & 31) * 32, k0 = (tl >> 5) * 32;
    const float* W = (w == 0) ? wq : (w == 1) ? wk : (w == 2) ? wv : wo;
    __half* T = g_w4[w];
    int tx = threadIdx.x & 31, ty = threadIdx.x >> 5;
    #pragma unroll
    for (int i = 0; i < 32; i += 8)
        t[ty + i][tx] = W[(size_t)(k0 + ty + i) * DM + n0 + tx];
    __syncthreads();
    #pragma unroll
    for (int i = 0; i < 32; i += 8) {
        float v = t[tx][ty + i];
        T[(size_t)(n0 + ty + i) * DM + k0 + tx] = __float2half_rn(v);
    }
}

// ---------------------------------------------------------------------------
// fp16 GEMM core: CTA tile 256x128, 512 threads (16 warps, 4M x 4N),
// warp tile 64x32, BK=32, double-buffered cp.async, 1 CTA/SM.
// ---------------------------------------------------------------------------
#define GBM 256
#define GBN 128
#define GBK 32
#define OA_B (256 * 80)       // A tile: 256 rows x 80 B
#define OW_B (128 * 80)       // W tile: 128 rows x 80 B
#define STAGE_B (OA_B + OW_B) // 30720
#define GEMM_SMEM (2 * STAGE_B)  // 61440
#define O_A 0
#define O_W OA_B

struct GemmAcc { float a[4][4][4]; };

__device__ __forceinline__ void gemm_mainloop(const __half* __restrict__ A,
                                              const __half* __restrict__ W,
                                              int bm, int bn, char* smem,
                                              GemmAcc& acc)
{
    const uint32_t sbase = smem_u32(smem);
    const int tid = threadIdx.x;
    const int lane = tid & 31;
    const int wid = tid >> 5;
    const int wm = wid & 3;     // 4 x 64 rows
    const int wn = wid >> 2;    // 4 x 32 cols

    #pragma unroll
    for (int i = 0; i < 4; i++)
        #pragma unroll
        for (int j = 0; j < 4; j++)
            #pragma unroll
            for (int e = 0; e < 4; e++) acc.a[i][j][e] = 0.f;

    const int lr = tid >> 2;        // 0..127
    const int lc = tid & 3;

    auto load_stage = [&](int buf, int k0) {
        uint32_t sb = sbase + buf * STAGE_B;
        cpa16(sb + O_A + lr * 80 + lc * 16,
              A + (size_t)(bm + lr) * DM + k0 + lc * 8);
        cpa16(sb + O_A + (128 + lr) * 80 + lc * 16,
              A + (size_t)(bm + 128 + lr) * DM + k0 + lc * 8);
        cpa16(sb + O_W + lr * 80 + lc * 16,
              W + (size_t)(bn + lr) * DM + k0 + lc * 8);
    };

    const int a_row = (lane & 7) + ((lane >> 3) & 1) * 8;
    const int a_kh  = (lane >> 4) * 8;
    const int b_n   = (lane & 7) + ((lane >> 4) & 1) * 8;
    const int b_kh  = ((lane >> 3) & 1) * 8;

    const int T = DM / GBK;
    load_stage(0, 0);
    cpa_commit();

    for (int t = 0; t < T; t++) {
        if (t + 1 < T) {
            load_stage((t + 1) & 1, (t + 1) * GBK);
            cpa_commit();
            asm volatile("cp.async.wait_group 1;" ::: "memory");
        } else {
            asm volatile("cp.async.wait_group 0;" ::: "memory");
        }
        __syncthreads();

        const uint32_t sb = sbase + (t & 1) * STAGE_B;
        #pragma unroll
        for (int ks = 0; ks < 2; ks++) {
            uint32_t af[4][4];
            #pragma unroll
            for (int mi = 0; mi < 4; mi++) {
                uint32_t ra = sb + O_A + (wm * 64 + mi * 16 + a_row) * 80
                            + (ks * 16 + a_kh) * 2;
                ldmx4(af[mi], ra);
            }
            #pragma unroll
            for (int np = 0; np < 2; np++) {
                uint32_t wf[4];
                uint32_t rb = sb + O_W + (wn * 32 + np * 16 + b_n) * 80
                            + (ks * 16 + b_kh) * 2;
                ldmx4(wf, rb);
                #pragma unroll
                for (int mi = 0; mi < 4; mi++) {
                    mmaf16(acc.a[mi][np * 2 + 0], af[mi], wf[0], wf[1]);
                    mmaf16(acc.a[mi][np * 2 + 1], af[mi], wf[2], wf[3]);
                }
            }
        }
        __syncthreads();
    }
}

// Fused QKV projection: blockIdx.z selects weight/bias/output.
__global__ __launch_bounds__(512, 1)
void gemm_qkv_kernel(const float* __restrict__ bq,
                     const float* __restrict__ bk,
                     const float* __restrict__ bv)
{
    extern __shared__ char smem[];
    const int z = blockIdx.z;
    const int bm = blockIdx.y * GBM;
    const int bn = blockIdx.x * GBN;
    const float* bias = (z == 0) ? bq : (z == 1) ? bk : bv;
    __half* Of = (z == 0) ? g_qf : (z == 1) ? g_kf : g_vf;
    const float qs = (z == 0) ? 0.125f : 1.f;

    GemmAcc acc;
    gemm_mainloop(g_xf, g_w4[z], bm, bn, smem, acc);

    const int lane = threadIdx.x & 31;
    const int wid = threadIdx.x >> 5;
    const int wm = wid & 3;
    const int wn = wid >> 2;

    #pragma unroll
    for (int mi = 0; mi < 4; mi++) {
        #pragma unroll
        for (int nf = 0; nf < 4; nf++) {
            int gcol = bn + wn * 32 + nf * 8 + (lane & 3) * 2;
            float b0 = __ldg(bias + gcol);
            float b1 = __ldg(bias + gcol + 1);
            #pragma unroll
            for (int half = 0; half < 2; half++) {
                int row = bm + wm * 64 + mi * 16 + (lane >> 2) + half * 8;
                float vx = (acc.a[mi][nf][half * 2 + 0] + b0) * qs;
                float vy = (acc.a[mi][nf][half * 2 + 1] + b1) * qs;
                int hh = gcol >> 6, d = gcol & 63;
                int b_ = row >> 11, s = row & 2047;
                if (z != 2) {
                    size_t o = ((((size_t)b_ * HH + hh) * SS + s) * DH) + d;
                    __half2 hv = __floats2half2_rn(vx, vy);
                    *(__half2*)&Of[o] = hv;
                } else {
                    size_t o = ((((size_t)b_ * HH + hh) * DH + d) * SS) + s;
                    Of[o] = __float2half_rn(vx);
                    Of[o + SS] = __float2half_rn(vy);
                }
            }
        }
    }
}

// Output projection: ctx(fp16) @ wo^T + bo -> fp32 out
__global__ __launch_bounds__(512, 1)
void gemm_out_kernel(const float* __restrict__ bias, float* __restrict__ C)
{
    extern __shared__ char smem[];
    const int bm = blockIdx.y * GBM;
    const int bn = blockIdx.x * GBN;

    GemmAcc acc;
    gemm_mainloop(g_cf, g_w4[3], bm, bn, smem, acc);

    const int lane = threadIdx.x & 31;
    const int wid = threadIdx.x >> 5;
    const int wm = wid & 3;
    const int wn = wid >> 2;

    #pragma unroll
    for (int mi = 0; mi < 4; mi++) {
        #pragma unroll
        for (int nf = 0; nf < 4; nf++) {
            int gcol = bn + wn * 32 + nf * 8 + (lane & 3) * 2;
            float b0 = __ldg(bias + gcol);
            float b1 = __ldg(bias + gcol + 1);
            #pragma unroll
            for (int half = 0; half < 2; half++) {
                int row = bm + wm * 64 + mi * 16 + (lane >> 2) + half * 8;
                float2 v;
                v.x = acc.a[mi][nf][half * 2 + 0] + b0;
                v.y = acc.a[mi][nf][half * 2 + 1] + b1;
                *(float2*)&C[(size_t)row * DM + gcol] = v;
            }
        }
    }
}

// ---------------------------------------------------------------------------
// Tensor-core flash attention, fp16, fp32 softmax. Q pre-scaled by 1/8.
// Q-tile 256 rows per CTA (512 thr, 16 warps x 16 q-rows) -> halves KV
// traffic. 64-key double-buffered chunks.
// ---------------------------------------------------------------------------
#define FQSZ (256 * 144)           // 36864
#define FKOFF 0
#define FVOFF (64 * 144)           // 9216
#define FSTAGE (2 * 64 * 144)      // 18432
#define FLASH_SMEM (FQSZ + 2 * FSTAGE)  // 73728

__global__ __launch_bounds__(512, 1)
void flash_fp16_kernel()
{
    extern __shared__ char smem[];
    const uint32_t sbase = smem_u32(smem);
    const int tid = threadIdx.x;
    const int lane = tid & 31;
    const int wid = tid >> 5;              // 0..15
    const int bh = blockIdx.y;
    const int q0 = blockIdx.x * 256;

    const size_t qbase = ((size_t)bh * SS + q0) * DH;
    const size_t kbase = (size_t)bh * SS * DH;
    const size_t vbase = (size_t)bh * DH * SS;

    // ---- load Q tile (256 x 64 fp16): 2048 chunks, 4/thread ----
    #pragma unroll
    for (int i = 0; i < 4; i++) {
        int c = tid + i * 512;
        int row = c >> 3, col = c & 7;
        cpa16(sbase + row * 144 + col * 16,
              g_qf + qbase + (size_t)row * DH + col * 8);
    }
    cpa_commit();

    auto load_kv = [&](int buf, int kv0) {
        uint32_t sb = sbase + FQSZ + buf * FSTAGE;
        int row = tid >> 3, col = tid & 7;   // 512 chunks per matrix, 1 each
        uint32_t so = row * 144 + col * 16;
        cpa16(sb + FKOFF + so, g_kf + kbase + (size_t)(kv0 + row) * DH + col * 8);
        cpa16(sb + FVOFF + so, g_vf + vbase + (size_t)row * SS + kv0 + col * 8);
    };

    load_kv(0, 0);
    cpa_commit();
    asm volatile("cp.async.wait_group 0;" ::: "memory");
    __syncthreads();

    const int a_row = (lane & 7) + ((lane >> 3) & 1) * 8;
    const int a_kh  = (lane >> 4) * 8;
    const int b_n   = (lane & 7) + ((lane >> 4) & 1) * 8;
    const int b_kh  = ((lane >> 3) & 1) * 8;

    float Oa[8][4];
    #pragma unroll
    for (int j = 0; j < 8; j++)
        #pragma unroll
        for (int e = 0; e < 4; e++) Oa[j][e] = 0.f;
    float m0 = -1e30f, m1 = -1e30f, l0 = 0.f, l1 = 0.f;

    const int T = SS / 64;
    for (int t = 0; t < T; t++) {
        if (t + 1 < T) {
            load_kv((t + 1) & 1, (t + 1) * 64);
            cpa_commit();
            asm volatile("cp.async.wait_group 1;" ::: "memory");
        } else {
            asm volatile("cp.async.wait_group 0;" ::: "memory");
        }
        __syncthreads();

        const uint32_t sb = sbase + FQSZ + (t & 1) * FSTAGE;

        // ---- S = Q K^T (Q pre-scaled) ----
        float S[8][4];
        #pragma unroll
        for (int j = 0; j < 8; j++)
            #pragma unroll
            for (int e = 0; e < 4; e++) S[j][e] = 0.f;

        #pragma unroll
        for (int ks = 0; ks < 4; ks++) {
            uint32_t qf4[4];
            ldmx4(qf4, sbase + (wid * 16 + a_row) * 144 + (ks * 16 + a_kh) * 2);
            #pragma unroll
            for (int np = 0; np < 4; np++) {
                uint32_t kf4[4];
                ldmx4(kf4, sb + FKOFF + (np * 16 + b_n) * 144 + (ks * 16 + b_kh) * 2);
                mmaf16(S[np * 2 + 0], qf4, kf4[0], kf4[1]);
                mmaf16(S[np * 2 + 1], qf4, kf4[2], kf4[3]);
            }
        }

        // ---- online softmax ----
        float rx0 = -1e30f, rx1 = -1e30f;
        #pragma unroll
        for (int j = 0; j < 8; j++) {
            rx0 = fmaxf(rx0, fmaxf(S[j][0], S[j][1]));
            rx1 = fmaxf(rx1, fmaxf(S[j][2], S[j][3]));
        }
        rx0 = fmaxf(rx0, __shfl_xor_sync(0xFFFFFFFF, rx0, 1));
        rx0 = fmaxf(rx0, __shfl_xor_sync(0xFFFFFFFF, rx0, 2));
        rx1 = fmaxf(rx1, __shfl_xor_sync(0xFFFFFFFF, rx1, 1));
        rx1 = fmaxf(rx1, __shfl_xor_sync(0xFFFFFFFF, rx1, 2));
        float mn0 = fmaxf(m0, rx0), mn1 = fmaxf(m1, rx1);
        if (mn0 != m0 || mn1 != m1) {
            float al0 = __expf(m0 - mn0), al1 = __expf(m1 - mn1);
            l0 *= al0; l1 *= al1;
            #pragma unroll
            for (int j = 0; j < 8; j++) {
                Oa[j][0] *= al0; Oa[j][1] *= al0;
                Oa[j][2] *= al1; Oa[j][3] *= al1;
            }
            m0 = mn0; m1 = mn1;
        }
        #pragma unroll
        for (int j = 0; j < 8; j++) {
            S[j][0] = __expf(S[j][0] - m0);
            S[j][1] = __expf(S[j][1] - m0);
            S[j][2] = __expf(S[j][2] - m1);
            S[j][3] = __expf(S[j][3] - m1);
            l0 += S[j][0] + S[j][1];
            l1 += S[j][2] + S[j][3];
        }

        // ---- O += P V ----
        #pragma unroll
        for (int kc = 0; kc < 4; kc++) {
            uint32_t pa[4];
            #pragma unroll
            for (int u = 0; u < 2; u++) {
                const float* sp = S[kc * 2 + u];
                pa[u * 2 + 0] = packh(sp[0], sp[1]);
                pa[u * 2 + 1] = packh(sp[2], sp[3]);
            }
            #pragma unroll
            for (int np = 0; np < 4; np++) {
                uint32_t vf4[4];
                ldmx4(vf4, sb + FVOFF + (np * 16 + b_n) * 144 + (kc * 16 + b_kh) * 2);
                mmaf16(Oa[np * 2 + 0], pa, vf4[0], vf4[1]);
                mmaf16(Oa[np * 2 + 1], pa, vf4[2], vf4[3]);
            }
        }
        __syncthreads();
    }

    // ---- finalize ----
    l0 += __shfl_xor_sync(0xFFFFFFFF, l0, 1);
    l0 += __shfl_xor_sync(0xFFFFFFFF, l0, 2);
    l1 += __shfl_xor_sync(0xFFFFFFFF, l1, 1);
    l1 += __shfl_xor_sync(0xFFFFFFFF, l1, 2);
    float inv0 = 1.f / l0, inv1 = 1.f / l1;

    const int b_ = bh >> 4, h = bh & 15;
    const int r0 = q0 + wid * 16 + (lane >> 2);
    const int col = h * 64 + (lane & 3) * 2;
    #pragma unroll
    for (int nf = 0; nf < 8; nf++) {
        #pragma unroll
        for (int half = 0; half < 2; half++) {
            float inv = half ? inv1 : inv0;
            float vx = Oa[nf][half * 2 + 0] * inv;
            float vy = Oa[nf][half * 2 + 1] * inv;
            size_t o = ((size_t)b_ * SS + r0 + half * 8) * DM + col + nf * 8;
            __half2 hv = __floats2half2_rn(vx, vy);
            *(__half2*)&g_cf[o] = hv;
        }
    }
}

// ---------------------------------------------------------------------------
extern "C" void kernel_launch(void* const* d_in, const int* in_sizes, int n_in,
                              void* d_out, int out_size)
{
    const float* x  = (const float*)d_in[0];
    const float* wq = (const float*)d_in[1];
    const float* bq = (const float*)d_in[2];
    const float* wk = (const float*)d_in[3];
    const float* bk = (const float*)d_in[4];
    const float* wv = (const float*)d_in[5];
    const float* bv = (const float*)d_in[6];
    const float* wo = (const float*)d_in[7];
    const float* bo = (const float*)d_in[8];
    float* out = (float*)d_out;

    cudaFuncSetAttribute(gemm_qkv_kernel,
                         cudaFuncAttributeMaxDynamicSharedMemorySize, GEMM_SMEM);
    cudaFuncSetAttribute(gemm_out_kernel,
                         cudaFuncAttributeMaxDynamicSharedMemorySize, GEMM_SMEM);
    cudaFuncSetAttribute(flash_fp16_kernel,
                         cudaFuncAttributeMaxDynamicSharedMemorySize, FLASH_SMEM);

    // 1) fused prep
    prep_kernel<<<8192, 256>>>(x, wq, wk, wv, wo);

    // 2) fused QKV projections (CTA tile 256x128)
    gemm_qkv_kernel<<<dim3(DM / GBN, MM / GBM, 3), 512, GEMM_SMEM>>>(bq, bk, bv);

    // 3) attention (Q tile 256)
    flash_fp16_kernel<<<dim3(SS / 256, BB * HH), 512, FLASH_SMEM>>>();

    // 4) output projection
    gemm_out_kernel<<<dim3(DM / GBN, MM / GBM), 512, GEMM_SMEM>>>(bo, out);
}

// round 15
// speedup vs baseline: 1.0569x; 1.0569x over previous
#include <cuda_runtime.h>
#include <cuda_fp16.h>
#include <math.h>
#include <stdint.h>

#define BB 2
#define HH 16
#define SS 2048
#define DH 64
#define DM 1024
#define MM (BB*SS)   // 4096

// ---------------------------------------------------------------------------
// Scratch (device globals)
// ---------------------------------------------------------------------------
__device__ __align__(256) __half g_xf[(size_t)MM*DM];
__device__ __align__(256) __half g_w4[4][(size_t)DM*DM];  // wq,wk,wv,wo [N,K]
// Q,K fp16 [B,H,S,DH] (Q pre-scaled by 1/8); V fp16 transposed [B,H,DH,S]
__device__ __align__(256) __half g_qf[(size_t)MM*DM];
__device__ __align__(256) __half g_kf[(size_t)MM*DM];
__device__ __align__(256) __half g_vf[(size_t)MM*DM];
// ctx fp16 (flash epilogue), row-major [MM, DM]
__device__ __align__(256) __half g_cf[(size_t)MM*DM];

// ---------------------------------------------------------------------------
// PTX helpers
// ---------------------------------------------------------------------------
__device__ __forceinline__ uint32_t smem_u32(const void* p) {
    uint32_t a;
    asm("{ .reg .u64 t; cvta.to.shared.u64 t, %1; cvt.u32.u64 %0, t; }"
        : "=r"(a) : "l"(p));
    return a;
}
__device__ __forceinline__ void cpa16(uint32_t s, const void* g) {
    asm volatile("cp.async.cg.shared.global [%0], [%1], 16;" :: "r"(s), "l"(g));
}
__device__ __forceinline__ void cpa_commit() {
    asm volatile("cp.async.commit_group;" ::: "memory");
}
__device__ __forceinline__ void ldmx4(uint32_t* r, uint32_t addr) {
    asm volatile("ldmatrix.sync.aligned.m8n8.x4.shared.b16 {%0,%1,%2,%3}, [%4];"
                 : "=r"(r[0]), "=r"(r[1]), "=r"(r[2]), "=r"(r[3]) : "r"(addr));
}
__device__ __forceinline__ void mmaf16(float* c, const uint32_t* a,
                                       uint32_t b0, uint32_t b1) {
    asm volatile(
        "mma.sync.aligned.m16n8k16.row.col.f32.f16.f16.f32 "
        "{%0,%1,%2,%3}, {%4,%5,%6,%7}, {%8,%9}, {%0,%1,%2,%3};"
        : "+f"(c[0]), "+f"(c[1]), "+f"(c[2]), "+f"(c[3])
        : "r"(a[0]), "r"(a[1]), "r"(a[2]), "r"(a[3]), "r"(b0), "r"(b1));
}
__device__ __forceinline__ uint32_t packh(float lo, float hi) {
    __half2 h = __floats2half2_rn(lo, hi);
    return *reinterpret_cast<uint32_t*>(&h);
}

// ---------------------------------------------------------------------------
// Fused prep: blocks [0,4096): x fp32->fp16; [4096,8192): weight transpose.
// ---------------------------------------------------------------------------
__global__ void prep_kernel(const float* __restrict__ x,
                            const float* __restrict__ wq,
                            const float* __restrict__ wk,
                            const float* __restrict__ wv,
                            const float* __restrict__ wo)
{
    int b = blockIdx.x;
    if (b < 4096) {
        int i = (b * 256 + threadIdx.x) * 4;
        float4 v = *(const float4*)(x + i);
        __half2 h0 = __floats2half2_rn(v.x, v.y);
        __half2 h1 = __floats2half2_rn(v.z, v.w);
        ((__half2*)(g_xf + i))[0] = h0;
        ((__half2*)(g_xf + i))[1] = h1;
        return;
    }
    __shared__ float t[32][33];
    int r = b - 4096;
    int w = r >> 10;
    int tl = r & 1023;
    int n0 = (tl & 31) * 32, k0 = (tl >> 5) * 32;
    const float* W = (w == 0) ? wq : (w == 1) ? wk : (w == 2) ? wv : wo;
    __half* T = g_w4[w];
    int tx = threadIdx.x & 31, ty = threadIdx.x >> 5;
    #pragma unroll
    for (int i = 0; i < 32; i += 8)
        t[ty + i][tx] = W[(size_t)(k0 + ty + i) * DM + n0 + tx];
    __syncthreads();
    #pragma unroll
    for (int i = 0; i < 32; i += 8) {
        float v = t[tx][ty + i];
        T[(size_t)(n0 + ty + i) * DM + k0 + tx] = __float2half_rn(v);
    }
}

// ---------------------------------------------------------------------------
// fp16 GEMM core: CTA tile 256x128, 512 threads (16 warps, 4M x 4N),
// warp tile 64x32, BK=32, 4-stage cp.async pipeline, ONE barrier/iter.
// ---------------------------------------------------------------------------
#define GBM 256
#define GBN 128
#define GBK 32
#define NSTAGE 4
#define OA_B (256 * 80)       // A tile: 256 rows x 80 B
#define OW_B (128 * 80)       // W tile: 128 rows x 80 B
#define STAGE_B (OA_B + OW_B) // 30720
#define GEMM_SMEM (NSTAGE * STAGE_B)  // 122880
#define O_A 0
#define O_W OA_B

struct GemmAcc { float a[4][4][4]; };

__device__ __forceinline__ void gemm_mainloop(const __half* __restrict__ A,
                                              const __half* __restrict__ W,
                                              int bm, int bn, char* smem,
                                              GemmAcc& acc)
{
    const uint32_t sbase = smem_u32(smem);
    const int tid = threadIdx.x;
    const int lane = tid & 31;
    const int wid = tid >> 5;
    const int wm = wid & 3;     // 4 x 64 rows
    const int wn = wid >> 2;    // 4 x 32 cols

    #pragma unroll
    for (int i = 0; i < 4; i++)
        #pragma unroll
        for (int j = 0; j < 4; j++)
            #pragma unroll
            for (int e = 0; e < 4; e++) acc.a[i][j][e] = 0.f;

    const int lr = tid >> 2;        // 0..127
    const int lc = tid & 3;

    auto load_stage = [&](int buf, int k0) {
        uint32_t sb = sbase + buf * STAGE_B;
        cpa16(sb + O_A + lr * 80 + lc * 16,
              A + (size_t)(bm + lr) * DM + k0 + lc * 8);
        cpa16(sb + O_A + (128 + lr) * 80 + lc * 16,
              A + (size_t)(bm + 128 + lr) * DM + k0 + lc * 8);
        cpa16(sb + O_W + lr * 80 + lc * 16,
              W + (size_t)(bn + lr) * DM + k0 + lc * 8);
        cpa_commit();
    };

    const int a_row = (lane & 7) + ((lane >> 3) & 1) * 8;
    const int a_kh  = (lane >> 4) * 8;
    const int b_n   = (lane & 7) + ((lane >> 4) & 1) * 8;
    const int b_kh  = ((lane >> 3) & 1) * 8;

    const int T = DM / GBK;   // 32

    // prologue: stages 0..2 in flight
    load_stage(0, 0);
    load_stage(1, GBK);
    load_stage(2, 2 * GBK);

    for (int t = 0; t < T; t++) {
        asm volatile("cp.async.wait_group %0;" :: "n"(NSTAGE - 2) : "memory");
        __syncthreads();

        // issue stage t+3 (writes buffer (t+3)%4 == (t-1)%4, safe post-barrier)
        if (t + 3 < T) load_stage((t + 3) & 3, (t + 3) * GBK);

        const uint32_t sb = sbase + (t & 3) * STAGE_B;
        #pragma unroll
        for (int ks = 0; ks < 2; ks++) {
            uint32_t af[4][4];
            #pragma unroll
            for (int mi = 0; mi < 4; mi++) {
                uint32_t ra = sb + O_A + (wm * 64 + mi * 16 + a_row) * 80
                            + (ks * 16 + a_kh) * 2;
                ldmx4(af[mi], ra);
            }
            #pragma unroll
            for (int np = 0; np < 2; np++) {
                uint32_t wf[4];
                uint32_t rb = sb + O_W + (wn * 32 + np * 16 + b_n) * 80
                            + (ks * 16 + b_kh) * 2;
                ldmx4(wf, rb);
                #pragma unroll
                for (int mi = 0; mi < 4; mi++) {
                    mmaf16(acc.a[mi][np * 2 + 0], af[mi], wf[0], wf[1]);
                    mmaf16(acc.a[mi][np * 2 + 1], af[mi], wf[2], wf[3]);
                }
            }
        }
    }
    __syncthreads();
}

// Fused QKV projection: blockIdx.z selects weight/bias/output.
__global__ __launch_bounds__(512, 1)
void gemm_qkv_kernel(const float* __restrict__ bq,
                     const float* __restrict__ bk,
                     const float* __restrict__ bv)
{
    extern __shared__ char smem[];
    const int z = blockIdx.z;
    const int bm = blockIdx.y * GBM;
    const int bn = blockIdx.x * GBN;
    const float* bias = (z == 0) ? bq : (z == 1) ? bk : bv;
    __half* Of = (z == 0) ? g_qf : (z == 1) ? g_kf : g_vf;
    const float qs = (z == 0) ? 0.125f : 1.f;

    GemmAcc acc;
    gemm_mainloop(g_xf, g_w4[z], bm, bn, smem, acc);

    const int lane = threadIdx.x & 31;
    const int wid = threadIdx.x >> 5;
    const int wm = wid & 3;
    const int wn = wid >> 2;

    #pragma unroll
    for (int mi = 0; mi < 4; mi++) {
        #pragma unroll
        for (int nf = 0; nf < 4; nf++) {
            int gcol = bn + wn * 32 + nf * 8 + (lane & 3) * 2;
            float b0 = __ldg(bias + gcol);
            float b1 = __ldg(bias + gcol + 1);
            #pragma unroll
            for (int half = 0; half < 2; half++) {
                int row = bm + wm * 64 + mi * 16 + (lane >> 2) + half * 8;
                float vx = (acc.a[mi][nf][half * 2 + 0] + b0) * qs;
                float vy = (acc.a[mi][nf][half * 2 + 1] + b1) * qs;
                int hh = gcol >> 6, d = gcol & 63;
                int b_ = row >> 11, s = row & 2047;
                if (z != 2) {
                    size_t o = ((((size_t)b_ * HH + hh) * SS + s) * DH) + d;
                    __half2 hv = __floats2half2_rn(vx, vy);
                    *(__half2*)&Of[o] = hv;
                } else {
                    size_t o = ((((size_t)b_ * HH + hh) * DH + d) * SS) + s;
                    Of[o] = __float2half_rn(vx);
                    Of[o + SS] = __float2half_rn(vy);
                }
            }
        }
    }
}

// Output projection: ctx(fp16) @ wo^T + bo -> fp32 out
__global__ __launch_bounds__(512, 1)
void gemm_out_kernel(const float* __restrict__ bias, float* __restrict__ C)
{
    extern __shared__ char smem[];
    const int bm = blockIdx.y * GBM;
    const int bn = blockIdx.x * GBN;

    GemmAcc acc;
    gemm_mainloop(g_cf, g_w4[3], bm, bn, smem, acc);

    const int lane = threadIdx.x & 31;
    const int wid = threadIdx.x >> 5;
    const int wm = wid & 3;
    const int wn = wid >> 2;

    #pragma unroll
    for (int mi = 0; mi < 4; mi++) {
        #pragma unroll
        for (int nf = 0; nf < 4; nf++) {
            int gcol = bn + wn * 32 + nf * 8 + (lane & 3) * 2;
            float b0 = __ldg(bias + gcol);
            float b1 = __ldg(bias + gcol + 1);
            #pragma unroll
            for (int half = 0; half < 2; half++) {
                int row = bm + wm * 64 + mi * 16 + (lane >> 2) + half * 8;
                float2 v;
                v.x = acc.a[mi][nf][half * 2 + 0] + b0;
                v.y = acc.a[mi][nf][half * 2 + 1] + b1;
                *(float2*)&C[(size_t)row * DM + gcol] = v;
            }
        }
    }
}

// ---------------------------------------------------------------------------
// Tensor-core flash attention, fp16, fp32 softmax (known-good R12 shape).
// Q pre-scaled by 1/8. 256 thr, 128-row Q tile, 64-key double-buffered,
// 2 CTAs/SM.
// ---------------------------------------------------------------------------
#define FQSZ (128 * 144)
#define FKOFF 0
#define FVOFF (64 * 144)
#define FSTAGE (2 * 64 * 144)
#define FLASH_SMEM (FQSZ + 2 * FSTAGE)  // 55296

__global__ __launch_bounds__(256, 2)
void flash_fp16_kernel()
{
    extern __shared__ char smem[];
    const uint32_t sbase = smem_u32(smem);
    const int tid = threadIdx.x;
    const int lane = tid & 31;
    const int wid = tid >> 5;
    const int bh = blockIdx.y;
    const int q0 = blockIdx.x * 128;

    const size_t qbase = ((size_t)bh * SS + q0) * DH;
    const size_t kbase = (size_t)bh * SS * DH;
    const size_t vbase = (size_t)bh * DH * SS;

    #pragma unroll
    for (int i = 0; i < 4; i++) {
        int c = tid + i * 256;
        int row = c >> 3, col = c & 7;
        cpa16(sbase + row * 144 + col * 16,
              g_qf + qbase + (size_t)row * DH + col * 8);
    }
    cpa_commit();

    auto load_kv = [&](int buf, int kv0) {
        uint32_t sb = sbase + FQSZ + buf * FSTAGE;
        #pragma unroll
        for (int i = 0; i < 2; i++) {
            int c = tid + i * 256;
            int row = c >> 3, col = c & 7;
            uint32_t so = row * 144 + col * 16;
            cpa16(sb + FKOFF + so, g_kf + kbase + (size_t)(kv0 + row) * DH + col * 8);
            cpa16(sb + FVOFF + so, g_vf + vbase + (size_t)row * SS + kv0 + col * 8);
        }
    };

    load_kv(0, 0);
    cpa_commit();
    asm volatile("cp.async.wait_group 0;" ::: "memory");
    __syncthreads();

    const int a_row = (lane & 7) + ((lane >> 3) & 1) * 8;
    const int a_kh  = (lane >> 4) * 8;
    const int b_n   = (lane & 7) + ((lane >> 4) & 1) * 8;
    const int b_kh  = ((lane >> 3) & 1) * 8;

    float Oa[8][4];
    #pragma unroll
    for (int j = 0; j < 8; j++)
        #pragma unroll
        for (int e = 0; e < 4; e++) Oa[j][e] = 0.f;
    float m0 = -1e30f, m1 = -1e30f, l0 = 0.f, l1 = 0.f;

    const int T = SS / 64;
    for (int t = 0; t < T; t++) {
        if (t + 1 < T) {
            load_kv((t + 1) & 1, (t + 1) * 64);
            cpa_commit();
            asm volatile("cp.async.wait_group 1;" ::: "memory");
        } else {
            asm volatile("cp.async.wait_group 0;" ::: "memory");
        }
        __syncthreads();

        const uint32_t sb = sbase + FQSZ + (t & 1) * FSTAGE;

        float S[8][4];
        #pragma unroll
        for (int j = 0; j < 8; j++)
            #pragma unroll
            for (int e = 0; e < 4; e++) S[j][e] = 0.f;

        #pragma unroll
        for (int ks = 0; ks < 4; ks++) {
            uint32_t qf4[4];
            ldmx4(qf4, sbase + (wid * 16 + a_row) * 144 + (ks * 16 + a_kh) * 2);
            #pragma unroll
            for (int np = 0; np < 4; np++) {
                uint32_t kf4[4];
                ldmx4(kf4, sb + FKOFF + (np * 16 + b_n) * 144 + (ks * 16 + b_kh) * 2);
                mmaf16(S[np * 2 + 0], qf4, kf4[0], kf4[1]);
                mmaf16(S[np * 2 + 1], qf4, kf4[2], kf4[3]);
            }
        }

        float rx0 = -1e30f, rx1 = -1e30f;
        #pragma unroll
        for (int j = 0; j < 8; j++) {
            rx0 = fmaxf(rx0, fmaxf(S[j][0], S[j][1]));
            rx1 = fmaxf(rx1, fmaxf(S[j][2], S[j][3]));
        }
        rx0 = fmaxf(rx0, __shfl_xor_sync(0xFFFFFFFF, rx0, 1));
        rx0 = fmaxf(rx0, __shfl_xor_sync(0xFFFFFFFF, rx0, 2));
        rx1 = fmaxf(rx1, __shfl_xor_sync(0xFFFFFFFF, rx1, 1));
        rx1 = fmaxf(rx1, __shfl_xor_sync(0xFFFFFFFF, rx1, 2));
        float mn0 = fmaxf(m0, rx0), mn1 = fmaxf(m1, rx1);
        if (mn0 != m0 || mn1 != m1) {
            float al0 = __expf(m0 - mn0), al1 = __expf(m1 - mn1);
            l0 *= al0; l1 *= al1;
            #pragma unroll
            for (int j = 0; j < 8; j++) {
                Oa[j][0] *= al0; Oa[j][1] *= al0;
                Oa[j][2] *= al1; Oa[j][3] *= al1;
            }
            m0 = mn0; m1 = mn1;
        }
        #pragma unroll
        for (int j = 0; j < 8; j++) {
            S[j][0] = __expf(S[j][0] - m0);
            S[j][1] = __expf(S[j][1] - m0);
            S[j][2] = __expf(S[j][2] - m1);
            S[j][3] = __expf(S[j][3] - m1);
            l0 += S[j][0] + S[j][1];
            l1 += S[j][2] + S[j][3];
        }

        #pragma unroll
        for (int kc = 0; kc < 4; kc++) {
            uint32_t pa[4];
            #pragma unroll
            for (int u = 0; u < 2; u++) {
                const float* sp = S[kc * 2 + u];
                pa[u * 2 + 0] = packh(sp[0], sp[1]);
                pa[u * 2 + 1] = packh(sp[2], sp[3]);
            }
            #pragma unroll
            for (int np = 0; np < 4; np++) {
                uint32_t vf4[4];
                ldmx4(vf4, sb + FVOFF + (np * 16 + b_n) * 144 + (kc * 16 + b_kh) * 2);
                mmaf16(Oa[np * 2 + 0], pa, vf4[0], vf4[1]);
                mmaf16(Oa[np * 2 + 1], pa, vf4[2], vf4[3]);
            }
        }
        __syncthreads();
    }

    l0 += __shfl_xor_sync(0xFFFFFFFF, l0, 1);
    l0 += __shfl_xor_sync(0xFFFFFFFF, l0, 2);
    l1 += __shfl_xor_sync(0xFFFFFFFF, l1, 1);
    l1 += __shfl_xor_sync(0xFFFFFFFF, l1, 2);
    float inv0 = 1.f / l0, inv1 = 1.f / l1;

    const int b_ = bh >> 4, h = bh & 15;
    const int r0 = q0 + wid * 16 + (lane >> 2);
    const int col = h * 64 + (lane & 3) * 2;
    #pragma unroll
    for (int nf = 0; nf < 8; nf++) {
        #pragma unroll
        for (int half = 0; half < 2; half++) {
            float inv = half ? inv1 : inv0;
            float vx = Oa[nf][half * 2 + 0] * inv;
            float vy = Oa[nf][half * 2 + 1] * inv;
            size_t o = ((size_t)b_ * SS + r0 + half * 8) * DM + col + nf * 8;
            __half2 hv = __floats2half2_rn(vx, vy);
            *(__half2*)&g_cf[o] = hv;
        }
    }
}

// ---------------------------------------------------------------------------
extern "C" void kernel_launch(void* const* d_in, const int* in_sizes, int n_in,
                              void* d_out, int out_size)
{
    const float* x  = (const float*)d_in[0];
    const float* wq = (const float*)d_in[1];
    const float* bq = (const float*)d_in[2];
    const float* wk = (const float*)d_in[3];
    const float* bk = (const float*)d_in[4];
    const float* wv = (const float*)d_in[5];
    const float* bv = (const float*)d_in[6];
    const float* wo = (const float*)d_in[7];
    const float* bo = (const float*)d_in[8];
    float* out = (float*)d_out;

    cudaFuncSetAttribute(gemm_qkv_kernel,
                         cudaFuncAttributeMaxDynamicSharedMemorySize, GEMM_SMEM);
    cudaFuncSetAttribute(gemm_out_kernel,
                         cudaFuncAttributeMaxDynamicSharedMemorySize, GEMM_SMEM);
    cudaFuncSetAttribute(flash_fp16_kernel,
                         cudaFuncAttributeMaxDynamicSharedMemorySize, FLASH_SMEM);

    // 1) fused prep
    prep_kernel<<<8192, 256>>>(x, wq, wk, wv, wo);

    // 2) fused QKV projections (256x128 tile, 4-stage pipeline)
    gemm_qkv_kernel<<<dim3(DM / GBN, MM / GBM, 3), 512, GEMM_SMEM>>>(bq, bk, bv);

    // 3) attention
    flash_fp16_kernel<<<dim3(SS / 128, BB * HH), 256, FLASH_SMEM>>>();

    // 4) output projection
    gemm_out_kernel<<<dim3(DM / GBN, MM / GBM), 512, GEMM_SMEM>>>(bo, out);
}